// round 11
// baseline (speedup 1.0000x reference)
#include <cuda_runtime.h>
#include <cstdint>
#include <cstddef>

// Problem constants
#define NB   8
#define CB   128
#define NC   1024          // NB*CB
#define HH   160
#define WW   160
#define NA   180
#define NR   180
#define AR   (NA*NR)       // 32400
#define PIX  (HH*WW)       // 25600
#define TPB  512

// Scratch in __device__ globals (no allocation allowed)
__device__ float         g_T[(size_t)AR * NC];       // transposed: T[a][r][nc]
__device__ unsigned char g_idx[(size_t)NA * PIX];    // r index table [a][y][x]
__device__ double        g_tab[2 * NA];              // cos/irho, sin/irho

// sorted walk orders (8 px of a 4x2 block, px = x + 4y), packed 3b per slot.
// Class boundaries at tan(theta) = 1, 2, 3 (and mirrors), snapped to the
// EXACT integer-degree intervals so the walk is truly sorted by rho:
//   cls0 [0,45]  cls1 [46,63]  cls2 [64,71]  cls3 [72,90]
//   cls4 [91,108] cls5 [109,116] cls6 [117,135] cls7 [136,179]
__device__ const unsigned c_ord[8] = {
    0u|(4u<<3)|(1u<<6)|(5u<<9)|(2u<<12)|(6u<<15)|(3u<<18)|(7u<<21),
    0u|(1u<<3)|(4u<<6)|(2u<<9)|(5u<<12)|(3u<<15)|(6u<<18)|(7u<<21),
    0u|(1u<<3)|(2u<<6)|(4u<<9)|(3u<<12)|(5u<<15)|(6u<<18)|(7u<<21),
    0u|(1u<<3)|(2u<<6)|(3u<<9)|(4u<<12)|(5u<<15)|(6u<<18)|(7u<<21),
    3u|(2u<<3)|(1u<<6)|(0u<<9)|(7u<<12)|(6u<<15)|(5u<<18)|(4u<<21),
    3u|(2u<<3)|(1u<<6)|(7u<<9)|(0u<<12)|(6u<<15)|(5u<<18)|(4u<<21),
    3u|(2u<<3)|(7u<<6)|(1u<<9)|(6u<<12)|(0u<<15)|(5u<<18)|(4u<<21),
    3u|(7u<<3)|(2u<<6)|(6u<<9)|(1u<<12)|(5u<<15)|(0u<<18)|(4u<<21)
};

// ---------------------------------------------------------------------------
// Kernel 0: trig table (fp64, once)
// ---------------------------------------------------------------------------
__global__ void tab_kernel()
{
    int a = threadIdx.x;
    if (a < NA) {
        const double PI = 3.14159265358979323846;
        double th = (double)a * (PI / 180.0);
        double irho = 227.0 / 180.0;   // (int(sqrt(160^2+160^2))+1)/180
        g_tab[a]      = cos(th) / irho;
        g_tab[NA + a] = sin(th) / irho;
    }
}

// ---------------------------------------------------------------------------
// Kernel 1: rho-index table (fp64 FMA-class ops only; matches numpy exactly)
// ---------------------------------------------------------------------------
__global__ void build_idx_kernel()
{
    const int a = blockIdx.y;
    double tc = g_tab[a], ts = g_tab[NA + a];
    int p = blockIdx.x * 256 + threadIdx.x;
    int y = p / WW, x = p - y * WW;
    double v = __dadd_rn(__dmul_rn((double)(x - 80), tc),
                         __dmul_rn((double)(y - 80), ts));
    int r = (int)rint(v) + 90;
    r = min(NR - 1, max(0, r));
    g_idx[(size_t)a * PIX + p] = (unsigned char)r;
}

// ---------------------------------------------------------------------------
// Kernel 2: transpose In[NC][AR] -> T[AR][NC]
// ---------------------------------------------------------------------------
__global__ void transpose_kernel(const float* __restrict__ in)
{
    __shared__ float tile[32][33];
    int ar0 = blockIdx.x * 32;
    int nc0 = blockIdx.y * 32;
    int tx = threadIdx.x;
    int ty = threadIdx.y;
    #pragma unroll
    for (int i = ty; i < 32; i += 8) {
        int ar = ar0 + tx;
        if (ar < AR) tile[i][tx] = in[(size_t)(nc0 + i) * AR + ar];
    }
    __syncthreads();
    #pragma unroll
    for (int i = ty; i < 32; i += 8) {
        int ar = ar0 + i;
        if (ar < AR) g_T[(size_t)ar * NC + nc0 + tx] = tile[tx][i];
    }
}

// ---------------------------------------------------------------------------
// Kernel 3: main inverse-Hough — direct-LDG version (no smem staging).
//   CTA = 16x8 pixel tile x 128 ch, 512 thr = 16 warps, 2 CTAs/SM.
//   Warp = one 4x2 pixel block; lane = 4 consecutive channels: each value
//   load is LDG.128 x 32 lanes = one full 512B row slice, perfectly
//   coalesced. 16 warps share the same ~12 rows per angle -> L1D-resident;
//   no barriers in the main loop, warps run free.
//   Exactly-sorted walk per angle class -> loads = range+1 (minimum) and
//   deltas in {0,1}: sw record = r0(8b) | 7 x 1b deltas.
// ---------------------------------------------------------------------------
__global__ void __launch_bounds__(TPB, 2) iht_main_kernel(float* __restrict__ out)
{
    __shared__ unsigned sw[16 * NA];                 // 11520 B

    const int tid = threadIdx.x;
    const int x0 = blockIdx.x * 16;
    const int y0 = blockIdx.y * 8;
    const int cz0 = blockIdx.z * 128;
    const int lane = tid & 31;
    const int w = tid >> 5;                          // warp = pixel block id

    // ---- build packed sorted-walk records: sw[blk*180 + a] ----
    for (int i = tid; i < 16 * NA; i += TPB) {
        int blk = i & 15, a = i >> 4;
        int cls = a <= 45 ? 0 : a <= 63 ? 1 : a <= 71 ? 2 : a <= 90 ? 3
                : a <= 108 ? 4 : a <= 116 ? 5 : a <= 135 ? 6 : 7;
        unsigned ord = c_ord[cls];
        const unsigned char* s = g_idx + (size_t)a * PIX
                                 + (y0 + 2 * (blk >> 2)) * WW + x0 + 4 * (blk & 3);
        unsigned t0 = *(const unsigned*)s;           // y=0 row: px 0..3
        unsigned t1 = *(const unsigned*)(s + WW);    // y=1 row: px 4..7
        int p = ord & 7;
        int prev = (int)(((p < 4 ? t0 : t1) >> (8 * (p & 3))) & 255u);
        unsigned wv = (unsigned)prev;                // absolute r0, 8 bits
        #pragma unroll
        for (int k = 1; k < 8; k++) {
            p = (ord >> (3 * k)) & 7;
            int cur = (int)(((p < 4 ? t0 : t1) >> (8 * (p & 3))) & 255u);
            wv |= ((unsigned)(cur - prev)) << (7 + k);   // delta in {0,1}
            prev = cur;
        }
        sw[blk * NA + a] = wv;
    }
    __syncthreads();

    // ---- accumulators: 8 px x 4 ch = 16 u64 (px index = x + 4y) ----
    unsigned long long acc[16];
    #pragma unroll
    for (int i = 0; i < 16; i++) acc[i] = 0ull;

#define STEP0(PX)                                                             \
    asm volatile("{\n\t"                                                      \
        ".reg .u32 rr;\n\t"                                                   \
        "bfe.u32 rr, %5, 0, 8;\n\t"                                           \
        "mad.wide.u32 %4, rr, 4096, %6;\n\t"                                  \
        "ld.global.nc.v2.u64 {%2, %3}, [%4];\n\t"                             \
        "add.rn.f32x2 %0, %0, %2;\n\t"                                        \
        "add.rn.f32x2 %1, %1, %3;\n\t"                                        \
        "}"                                                                   \
        : "+l"(acc[2*(PX)]), "+l"(acc[2*(PX)+1]),                             \
          "+l"(v0), "+l"(v1), "=l"(ad)                                        \
        : "r"(wv), "l"(abase))

#define STEPD(PX, K)                                                          \
    asm volatile("{\n\t"                                                      \
        ".reg .pred p;\n\t .reg .u32 d;\n\t"                                  \
        "bfe.u32 d, %5, %6, 1;\n\t"                                           \
        "setp.ne.u32 p, d, 0;\n\t"                                            \
        "mad.wide.u32 %4, d, 4096, %4;\n\t"                                   \
        "@p ld.global.nc.v2.u64 {%2, %3}, [%4];\n\t"                          \
        "add.rn.f32x2 %0, %0, %2;\n\t"                                        \
        "add.rn.f32x2 %1, %1, %3;\n\t"                                        \
        "}"                                                                   \
        : "+l"(acc[2*(PX)]), "+l"(acc[2*(PX)+1]),                             \
          "+l"(v0), "+l"(v1), "+l"(ad)                                        \
        : "r"(wv), "n"(7 + (K)))

#define DOSEG(A0, A1, Q0,Q1,Q2,Q3,Q4,Q5,Q6,Q7)                                \
    for (int a = (A0); a < (A1); a++) {                                       \
        unsigned wv = sw[swb + a];                                            \
        unsigned long long abase = gT0 + (unsigned long long)a * (NR*NC*4ull);\
        unsigned long long v0 = 0, v1 = 0, ad;                                \
        STEP0(Q0);    STEPD(Q1,1); STEPD(Q2,2); STEPD(Q3,3);                  \
        STEPD(Q4,4);  STEPD(Q5,5); STEPD(Q6,6); STEPD(Q7,7);                  \
    }

    const unsigned swb = w * NA;
    const unsigned long long gT0 =
        (unsigned long long)(uintptr_t)((const char*)g_T
                                        + ((size_t)cz0 + lane * 4) * 4);

    DOSEG(  0,  46, 0,4,1,5,2,6,3,7);
    DOSEG( 46,  64, 0,1,4,2,5,3,6,7);
    DOSEG( 64,  72, 0,1,2,4,3,5,6,7);
    DOSEG( 72,  91, 0,1,2,3,4,5,6,7);
    DOSEG( 91, 109, 3,2,1,0,7,6,5,4);
    DOSEG(109, 117, 3,2,1,7,0,6,5,4);
    DOSEG(117, 136, 3,2,7,1,6,0,5,4);
    DOSEG(136, 180, 3,7,2,6,1,5,0,4);
#undef DOSEG
#undef STEPD
#undef STEP0

    // ---- epilogue: per ch, per row: float4 over the 4-wide block ----
    const int gx = x0 + 4 * (w & 3);
    const int gy = y0 + 2 * (w >> 2);
    const int c0 = cz0 + lane * 4;
    #pragma unroll
    for (int y = 0; y < 2; y++) {
        #pragma unroll
        for (int cc = 0; cc < 4; cc++) {
            int half = cc & 1, sel = cc >> 1;
            float4 o;
            unsigned long long s0 = acc[(0 + 4*y)*2 + sel];
            unsigned long long s1 = acc[(1 + 4*y)*2 + sel];
            unsigned long long s2 = acc[(2 + 4*y)*2 + sel];
            unsigned long long s3 = acc[(3 + 4*y)*2 + sel];
            o.x = __uint_as_float(half ? (unsigned)(s0 >> 32) : (unsigned)s0);
            o.y = __uint_as_float(half ? (unsigned)(s1 >> 32) : (unsigned)s1);
            o.z = __uint_as_float(half ? (unsigned)(s2 >> 32) : (unsigned)s2);
            o.w = __uint_as_float(half ? (unsigned)(s3 >> 32) : (unsigned)s3);
            *(float4*)(out + (size_t)(c0 + cc) * PIX + (gy + y) * WW + gx) = o;
        }
    }
}

// ---------------------------------------------------------------------------
extern "C" void kernel_launch(void* const* d_in, const int* in_sizes, int n_in,
                              void* d_out, int out_size)
{
    const float* hough = (const float*)d_in[0];
    float* out = (float*)d_out;

    tab_kernel<<<1, 256>>>();
    build_idx_kernel<<<dim3(PIX / 256, NA), 256>>>();
    transpose_kernel<<<dim3((AR + 31) / 32, NC / 32), dim3(32, 8)>>>(hough);
    iht_main_kernel<<<dim3(10, 20, 8), TPB>>>(out);
}